// round 17
// baseline (speedup 1.0000x reference)
#include <cuda_runtime.h>
#include <cstdint>

#define MM 1024
#define NN 4096
#define TCAND 4
#define FULLMASK 0xffffffffu

typedef unsigned int       u32;
typedef unsigned long long u64;

// ---------------- device scratch (no allocations allowed) ----------------
__device__ int   g_colhit[NN];
__device__ u32   g_colbits[NN / 32];
__device__ float g_rowmax[MM];
__device__ float g_rowsum[MM];
__device__ u64   g_cand[MM * TCAND];   // per-row top-4: key<<32 | col
__device__ float g_gmax;
__device__ float g_gsum;

// Monotonic float -> uint32 ordering key (nonzero for all real floats).
__device__ __forceinline__ u32 orderKey(float v) {
    u32 b = __float_as_uint(v);
    return (b & 0x80000000u) ? ~b : (b | 0x80000000u);
}

// Packed head: key high, inverted flat index (row<<12|col) low 23 bits.
// u64 max == (max key, then smallest flat index) — exact reference tie-break.
__device__ __forceinline__ u64 packHead(u32 key, u32 rc) {
    return ((u64)key << 23) | (u64)(0x400000u - rc);
}

__device__ __forceinline__ u64 u64max(u64 a, u64 b) { return a > b ? a : b; }

// insert into descending top-4 (x1 >= x2 >= x3 >= x4)
#define INS4(h) do { u64 _h = (h); \
    if (_h > x3) { \
        if (_h > x1)      { x4 = x3; x3 = x2; x2 = x1; x1 = _h; } \
        else if (_h > x2) { x4 = x3; x3 = x2; x2 = _h; } \
        else              { x4 = x3; x3 = _h; } \
    } else if (_h > x4) x4 = _h; } while (0)

// ---------------- K0: column-hit mask (bytes + bitmask) ------------------
__global__ void k0_colhit(const int* __restrict__ cont, const int* __restrict__ prev) {
    int tid = threadIdx.x;                 // 1024 threads
    #pragma unroll
    for (int k = 0; k < 4; k++) g_colhit[tid + k * 1024] = 0;
    if (tid < NN / 32) g_colbits[tid] = 0;
    __syncthreads();
    if (cont[tid]) {
        int c = prev[tid];
        g_colhit[c] = 1;                                  // benign races
        atomicOr(&g_colbits[c >> 5], 1u << (c & 31));
    }
}

// ---------------- K1: per-row rowmax, sumexp, top-4 masked candidates ----
__global__ void __launch_bounds__(256) k1_row(const float* __restrict__ scores,
                                              const int* __restrict__ cont) {
    const int r = blockIdx.x, tid = threadIdx.x, lane = tid & 31, warp = tid >> 5;
    __shared__ float wf[8];
    __shared__ float s_bcast;
    __shared__ u64   wtop[32];             // 8 warps x 4 candidates

    const float4* row = (const float4*)(scores + (size_t)r * NN);
    const bool isCont = (cont[r] != 0);    // uniform per block

    float vals[16];
    int   fidx[4];
    #pragma unroll
    for (int k = 0; k < 4; k++) {
        int f = tid + k * 256; fidx[k] = f;
        float4 v = row[f];
        vals[k * 4 + 0] = v.x; vals[k * 4 + 1] = v.y;
        vals[k * 4 + 2] = v.z; vals[k * 4 + 3] = v.w;
    }

    // ---- raw row max ----
    float m = vals[0];
    #pragma unroll
    for (int e = 1; e < 16; e++) m = fmaxf(m, vals[e]);
    #pragma unroll
    for (int off = 16; off; off >>= 1) m = fmaxf(m, __shfl_xor_sync(FULLMASK, m, off));
    if (lane == 0) wf[warp] = m;
    __syncthreads();
    if (warp == 0) {
        float t = (lane < 8) ? wf[lane] : -3.4e38f;
        #pragma unroll
        for (int off = 4; off; off >>= 1) t = fmaxf(t, __shfl_xor_sync(FULLMASK, t, off));
        if (lane == 0) { s_bcast = t; g_rowmax[r] = t; }
    }
    __syncthreads();
    float rowmax = s_bcast;

    // ---- row sumexp (stable at rowmax) ----
    float s = 0.f;
    #pragma unroll
    for (int e = 0; e < 16; e++) s += __expf(vals[e] - rowmax);
    #pragma unroll
    for (int off = 16; off; off >>= 1) s += __shfl_xor_sync(FULLMASK, s, off);
    __syncthreads();
    if (lane == 0) wf[warp] = s;
    __syncthreads();
    if (warp == 0) {
        float t = (lane < 8) ? wf[lane] : 0.f;
        #pragma unroll
        for (int off = 4; off; off >>= 1) t += __shfl_xor_sync(FULLMASK, t, off);
        if (lane == 0) g_rowsum[r] = t;
    }

    // ---- continuing rows: empty candidate list, done (uniform branch) ----
    if (isCont) {
        if (tid < TCAND) g_cand[r * TCAND + tid] = 0ull;
        return;
    }

    // ---- pack once: key<<13 | (4096-col); u64 max == exact tie-break ----
    u64 pk[16];
    #pragma unroll
    for (int k = 0; k < 4; k++) {
        int4 h = ((const int4*)g_colhit)[fidx[k]];
        int hv[4] = { h.x, h.y, h.z, h.w };
        #pragma unroll
        for (int j = 0; j < 4; j++) {
            int col = fidx[k] * 4 + j;
            pk[k * 4 + j] = hv[j] ? 0ull
                : (((u64)orderKey(vals[k * 4 + j]) << 13) | (u64)(4096 - col));
        }
    }

    // ---- warp-local top-4 (4 shuffle rounds, no barriers) ----
    #pragma unroll
    for (int round = 0; round < TCAND; round++) {
        u64 b = 0;
        #pragma unroll
        for (int e = 0; e < 16; e++) b = u64max(b, pk[e]);
        #pragma unroll
        for (int off = 16; off; off >>= 1)
            b = u64max(b, __shfl_xor_sync(FULLMASK, b, off));
        if (lane == 0) wtop[warp * 4 + round] = b;
        if (b) {
            #pragma unroll
            for (int e = 0; e < 16; e++) if (pk[e] == b) pk[e] = 0ull;
        }
    }
    __syncthreads();                        // single barrier

    // ---- warp 0 merges 32 candidates (one per lane) into row top-4 ----
    if (warp == 0) {
        u64 mine = wtop[lane];
        #pragma unroll
        for (int round = 0; round < TCAND; round++) {
            u64 b = mine;
            #pragma unroll
            for (int off = 16; off; off >>= 1)
                b = u64max(b, __shfl_xor_sync(FULLMASK, b, off));
            if (lane == 0) {
                u32 key = (u32)(b >> 13);
                u32 col = 4096u - (u32)(b & 0x1FFFu);
                g_cand[r * TCAND + round] = b ? (((u64)key << 32) | col) : 0ull;
            }
            if (b && mine == b) mine = 0ull;
        }
    }
}

// ---------------- K2: global max + global sum (from row stats) -----------
__global__ void __launch_bounds__(1024) k2_global() {
    int tid = threadIdx.x, lane = tid & 31, warp = tid >> 5;
    __shared__ float w[32];
    __shared__ float s_gm;
    float rm = g_rowmax[tid];
    float m = rm;
    #pragma unroll
    for (int off = 16; off; off >>= 1) m = fmaxf(m, __shfl_xor_sync(FULLMASK, m, off));
    if (lane == 0) w[warp] = m;
    __syncthreads();
    if (warp == 0) {
        float t = w[lane];
        #pragma unroll
        for (int off = 16; off; off >>= 1) t = fmaxf(t, __shfl_xor_sync(FULLMASK, t, off));
        if (lane == 0) s_gm = t;
    }
    __syncthreads();
    float gm = s_gm;
    float s = g_rowsum[tid] * __expf(rm - gm);
    #pragma unroll
    for (int off = 16; off; off >>= 1) s += __shfl_xor_sync(FULLMASK, s, off);
    __syncthreads();
    if (lane == 0) w[warp] = s;
    __syncthreads();
    if (warp == 0) {
        float t = w[lane];
        #pragma unroll
        for (int off = 16; off; off >>= 1) t += __shfl_xor_sync(FULLMASK, t, off);
        if (lane == 0) { g_gmax = gm; g_gsum = t; }
    }
}

// ---------------- K45: fused policy write + greedy assignment ------------
// Change vs 68.1us version: lanes offer their top-3 heads (96 offers/batch);
// hidden bound is p4. Same phase structure; claim-max dup resolution.
#define OFF_SHEADS 0
#define OFF_SCAND  8192
#define OFF_CLAIM  40960          /* u64 claim-max array: 32KB */
#define OFF_SGT    73728          /* 512 u64: top-4 per (lane,group) */
#define OFF_COLB   77824
#define OFF_HPTR   78336
#define OFF_MISC   79360
#define DSMEM      79872

// rebuild group gc's cached top-4
#define REBUILD4(gc) do { \
    u64 x1 = 0, x2 = 0, x3 = 0, x4 = 0; \
    const ulonglong2* _gp = (const ulonglong2*)(sheads + base + (gc) * 8); \
    _Pragma("unroll") \
    for (int _q = 0; _q < 4; _q++) { ulonglong2 _hh = _gp[_q]; INS4(_hh.x); INS4(_hh.y); } \
    sgt[(lane << 2) + (gc)] = x1; \
    sgt[128 + (lane << 2) + (gc)] = x2; \
    sgt[256 + (lane << 2) + (gc)] = x3; \
    sgt[384 + (lane << 2) + (gc)] = x4; \
} while (0)

#define LANETOPS4() do { \
    u64 x1 = 0, x2 = 0, x3 = 0, x4 = 0; \
    _Pragma("unroll") \
    for (int _g = 0; _g < 4; _g++) { \
        INS4(sgt[(lane << 2) + _g]); \
        INS4(sgt[128 + (lane << 2) + _g]); \
        INS4(sgt[256 + (lane << 2) + _g]); \
        INS4(sgt[384 + (lane << 2) + _g]); \
    } \
    p1 = x1; p2 = x2; p3 = x3; p4 = x4; \
} while (0)

__global__ void __launch_bounds__(1024, 1) k45_fused(
        const float* __restrict__ scores,
        const int* __restrict__ cont,
        const int* __restrict__ prev,
        float* __restrict__ out) {
    extern __shared__ char dyn[];
    const int tid = threadIdx.x;

    if (blockIdx.x < 512) {
        // ================= policy =================
        const float gm = g_gmax;
        const float inv = 1.0f / g_gsum;
        int i = blockIdx.x * 1024 + tid;
        const float4* p = (const float4*)scores;
        float4* o = (float4*)(out + MM);
        float4 a = p[i];
        float4 b = p[i + 524288];
        float4 ra, rb;
        ra.x = __expf(a.x - gm) * inv; ra.y = __expf(a.y - gm) * inv;
        ra.z = __expf(a.z - gm) * inv; ra.w = __expf(a.w - gm) * inv;
        rb.x = __expf(b.x - gm) * inv; rb.y = __expf(b.y - gm) * inv;
        rb.z = __expf(b.z - gm) * inv; rb.w = __expf(b.w - gm) * inv;
        o[i] = ra;
        o[i + 524288] = rb;
        return;
    }

    // ================= assignment (block 512) =================
    u64* sheads = (u64*)(dyn + OFF_SHEADS);
    u64* scand  = (u64*)(dyn + OFF_SCAND);
    u64* claim  = (u64*)(dyn + OFF_CLAIM);
    u64* sgt    = (u64*)(dyn + OFF_SGT);
    u32* colbits = (u32*)(dyn + OFF_COLB);
    unsigned char* hptr = (unsigned char*)(dyn + OFF_HPTR);
    int* misc = (int*)(dyn + OFF_MISC);
    float* out_act = out;

    // -------- prologue: full block builds shared state --------
    #pragma unroll
    for (int k = 0; k < TCAND; k++) {
        int idx = tid + k * 1024;
        scand[idx] = g_cand[idx];
        claim[idx] = 0ull;
    }
    if (tid < NN / 32) colbits[tid] = g_colbits[tid];
    {
        u64 c0 = g_cand[tid * TCAND];
        u32 key = (u32)(c0 >> 32);
        u32 col = (u32)c0 & 0xFFFu;
        sheads[tid] = key ? packHead(key, ((u32)tid << 12) | col) : 0ull;
    }
    hptr[tid] = 1;
    int myCont = cont[tid];
    out_act[tid] = myCont ? (float)prev[tid] : -1.0f;
    int K = __syncthreads_count(myCont == 0);
    if (tid == 0) misc[0] = K;
    __syncthreads();
    if (tid >= 32) return;

    const int lane = tid;
    const int base = lane * 32;
    const int K2 = misc[0];

    u64 p1, p2, p3, p4;
    { REBUILD4(0); REBUILD4(1); REBUILD4(2); REBUILD4(3); }
    LANETOPS4();

    int assigned = 0;
    int guard = 0;

    while (assigned < K2) {
        if (++guard > 16384) break;                  // safety (never hit)

        // ---- offers: lane's top-3 heads (distinct rows) ----
        bool l1 = (p1 != 0ull), l2 = (p2 != 0ull), l3 = (p3 != 0ull);
        u32 rc1 = 0x400000u - (u32)(p1 & 0x7FFFFFu);
        u32 rc2 = 0x400000u - (u32)(p2 & 0x7FFFFFu);
        u32 rc3 = 0x400000u - (u32)(p3 & 0x7FFFFFu);
        int r1 = (int)(rc1 >> 12), c1 = (int)(rc1 & 0xFFFu);
        int r2 = (int)(rc2 >> 12), c2 = (int)(rc2 & 0xFFFu);
        int r3 = (int)(rc3 >> 12), c3 = (int)(rc3 & 0xFFFu);

        // ---- stale at batch start ----
        bool s1 = l1 && ((colbits[c1 >> 5] >> (c1 & 31)) & 1u);
        bool s2 = l2 && ((colbits[c2 >> 5] >> (c2 & 31)) & 1u);
        bool s3 = l3 && ((colbits[c3 >> 5] >> (c3 & 31)) & 1u);

        // ---- dup resolution among live offers: claim-max per column ----
        bool w1 = l1 && !s1, w2 = l2 && !s2, w3 = l3 && !s3;
        if (w1) atomicMax(&claim[c1], p1);
        if (w2) atomicMax(&claim[c2], p2);
        if (w3) atomicMax(&claim[c3], p3);
        __syncwarp(FULLMASK);
        bool d1 = w1 && (claim[c1] != p1);     // loser of a column contest
        bool d2 = w2 && (claim[c2] != p2);
        bool d3 = w3 && (claim[c3] != p3);
        __syncwarp(FULLMASK);
        if (w1) claim[c1] = 0ull;              // same-addr same-val: benign
        if (w2) claim[c2] = 0ull;
        if (w3) claim[c3] = 0ull;

        // ---- cutoff S = max(hidden bound p4, stale/loser offer values) ----
        u64 contrib = p4;
        if (s1 || d1) contrib = u64max(contrib, p1);
        if (s2 || d2) contrib = u64max(contrib, p2);
        if (s3 || d3) contrib = u64max(contrib, p3);
        u32 chi = (u32)(contrib >> 32);
        u32 mh = __reduce_max_sync(FULLMASK, chi);
        u32 clo = (chi == mh) ? (u32)contrib : 0u;
        u32 ml = __reduce_max_sync(FULLMASK, clo);
        u64 S = ((u64)mh << 32) | ml;

        // ---- parallel commits (winners only; exact greedy prefix) ----
        bool k1c = w1 && !d1 && (p1 > S);
        bool k2c = w2 && !d2 && (p2 > S);
        bool k3c = w3 && !d3 && (p3 > S);
        if (k1c) { atomicOr(&colbits[c1 >> 5], 1u << (c1 & 31));
                   out_act[r1] = (float)c1; sheads[r1] = 0ull; }
        if (k2c) { atomicOr(&colbits[c2 >> 5], 1u << (c2 & 31));
                   out_act[r2] = (float)c2; sheads[r2] = 0ull; }
        if (k3c) { atomicOr(&colbits[c3 >> 5], 1u << (c3 & 31));
                   out_act[r3] = (float)c3; sheads[r3] = 0ull; }
        u32 cb1 = __ballot_sync(FULLMASK, k1c);
        u32 cb2 = __ballot_sync(FULLMASK, k2c);
        u32 cb3 = __ballot_sync(FULLMASK, k3c);
        assigned += __popc(cb1) + __popc(cb2) + __popc(cb3);
        __syncwarp(FULLMASK);

        // ---- fallback single-commit when batch was empty ----
        if (!(cb1 | cb2 | cb3)) {
            u32 key = (u32)(p1 >> 23);
            u32 mk = __reduce_max_sync(FULLMASK, key);
            if (mk == 0) break;                       // nothing left (uniform)
            u32 cnd = (key == mk) ? (u32)(p1 & 0x7FFFFFu) : 0u;
            u32 sel = __reduce_max_sync(FULLMASK, cnd);
            u32 rcf = 0x400000u - sel;
            int af = (int)(rcf >> 12), tf = (int)(rcf & 0xFFFu);
            u32 w = colbits[tf >> 5];                 // uniform read
            if (!((w >> (tf & 31)) & 1u)) {
                colbits[tf >> 5] = w | (1u << (tf & 31));   // replicated
                out_act[af] = (float)tf;
                sheads[af] = 0ull;
                assigned++;
                if (lane == (af >> 5)) k1c = true;    // af == r1 for owner
            }
            // if stale: pop phase below handles it
        }

        // ---- pop phase: recheck my offered rows vs updated colbits ----
        bool ch1 = k1c, ch2 = k2c, ch3 = k3c;
        int rsA = -1, rsB = -1, rsC = -1;
        if (l1) {
            u64 h = sheads[r1];
            if (h) {
                u32 hc = (0x400000u - (u32)(h & 0x7FFFFFu)) & 0xFFFu;
                if ((colbits[hc >> 5] >> (hc & 31)) & 1u) {
                    int p = hptr[r1]; u64 np = 0ull;
                    if (p < TCAND) {
                        while (p < TCAND) {
                            u64 cd = scand[(r1 << 2) + p]; p++;
                            u32 kk = (u32)(cd >> 32);
                            if (!kk) { p = TCAND; break; }
                            u32 cc = (u32)cd & 0xFFFu;
                            if (!((colbits[cc >> 5] >> (cc & 31)) & 1u)) {
                                np = packHead(kk, ((u32)r1 << 12) | cc); break;
                            }
                        }
                        hptr[r1] = (unsigned char)p;
                    }
                    if (np) sheads[r1] = np; else rsA = r1;
                    ch1 = true;
                }
            }
        }
        if (l2) {
            u64 h = sheads[r2];
            if (h) {
                u32 hc = (0x400000u - (u32)(h & 0x7FFFFFu)) & 0xFFFu;
                if ((colbits[hc >> 5] >> (hc & 31)) & 1u) {
                    int p = hptr[r2]; u64 np = 0ull;
                    if (p < TCAND) {
                        while (p < TCAND) {
                            u64 cd = scand[(r2 << 2) + p]; p++;
                            u32 kk = (u32)(cd >> 32);
                            if (!kk) { p = TCAND; break; }
                            u32 cc = (u32)cd & 0xFFFu;
                            if (!((colbits[cc >> 5] >> (cc & 31)) & 1u)) {
                                np = packHead(kk, ((u32)r2 << 12) | cc); break;
                            }
                        }
                        hptr[r2] = (unsigned char)p;
                    }
                    if (np) sheads[r2] = np; else rsB = r2;
                    ch2 = true;
                }
            }
        }
        if (l3) {
            u64 h = sheads[r3];
            if (h) {
                u32 hc = (0x400000u - (u32)(h & 0x7FFFFFu)) & 0xFFFu;
                if ((colbits[hc >> 5] >> (hc & 31)) & 1u) {
                    int p = hptr[r3]; u64 np = 0ull;
                    if (p < TCAND) {
                        while (p < TCAND) {
                            u64 cd = scand[(r3 << 2) + p]; p++;
                            u32 kk = (u32)(cd >> 32);
                            if (!kk) { p = TCAND; break; }
                            u32 cc = (u32)cd & 0xFFFu;
                            if (!((colbits[cc >> 5] >> (cc & 31)) & 1u)) {
                                np = packHead(kk, ((u32)r3 << 12) | cc); break;
                            }
                        }
                        hptr[r3] = (unsigned char)p;
                    }
                    if (np) sheads[r3] = np; else rsC = r3;
                    ch3 = true;
                }
            }
        }

        // ---- rare: warp-cooperative exact rescans (list exhausted) ----
        for (;;) {
            int my = (rsA >= 0) ? rsA : ((rsB >= 0) ? rsB : rsC);
            u32 rb = __ballot_sync(FULLMASK, my >= 0);
            if (!rb) break;
            int ln = __ffs((int)rb) - 1;
            int ra = __shfl_sync(FULLMASK, my, ln);
            const float4* rp = (const float4*)(scores + (size_t)ra * NN);
            u32 bk = 0, bc = 0xFFFu;
            #pragma unroll 4
            for (int q = 0; q < 32; q++) {
                int f = lane + q * 32;
                float4 vv = rp[f];
                int c0i = f * 4;
                float arr[4] = { vv.x, vv.y, vv.z, vv.w };
                #pragma unroll
                for (int j = 0; j < 4; j++) {
                    int cc = c0i + j;
                    if (!((colbits[cc >> 5] >> (cc & 31)) & 1u)) {
                        u32 kk = orderKey(arr[j]);
                        if (kk > bk) { bk = kk; bc = (u32)cc; }
                    }
                }
            }
            u32 mk2 = __reduce_max_sync(FULLMASK, bk);
            u32 pc = (bk == mk2) ? (0x1000u - bc) : 0u;
            u32 ps = __reduce_max_sync(FULLMASK, pc);
            if (lane == ln) {
                sheads[ra] = mk2 ? packHead(mk2, ((u32)ra << 12) | (0x1000u - ps)) : 0ull;
                hptr[ra] = TCAND;
                if (rsA == ra) rsA = -1;
                else if (rsB == ra) rsB = -1;
                else rsC = -1;
            }
        }
        __syncwarp(FULLMASK);

        // ---- refresh changed groups + lane tops ----
        if (ch1 || ch2 || ch3) {
            u32 gd = 0;
            if (ch1) gd |= 1u << ((r1 >> 3) & 3);
            if (ch2) gd |= 1u << ((r2 >> 3) & 3);
            if (ch3) gd |= 1u << ((r3 >> 3) & 3);
            if (gd & 1u) REBUILD4(0);
            if (gd & 2u) REBUILD4(1);
            if (gd & 4u) REBUILD4(2);
            if (gd & 8u) REBUILD4(3);
            LANETOPS4();
        }
    }
}

// ---------------- launch ---------------------------------------------------
extern "C" void kernel_launch(void* const* d_in, const int* in_sizes, int n_in,
                              void* d_out, int out_size) {
    const float* scores = (const float*)d_in[0];
    const int*   cont   = (const int*)d_in[1];
    const int*   prev   = (const int*)d_in[2];
    float* out = (float*)d_out;      // [0..1023] actions, [1024..] policy

    cudaFuncSetAttribute(k45_fused, cudaFuncAttributeMaxDynamicSharedMemorySize, DSMEM);

    k0_colhit<<<1, 1024>>>(cont, prev);
    k1_row<<<MM, 256>>>(scores, cont);
    k2_global<<<1, 1024>>>();
    k45_fused<<<513, 1024, DSMEM>>>(scores, cont, prev, out);
}